// round 16
// baseline (speedup 1.0000x reference)
#include <cuda_runtime.h>
#include <cuda_fp16.h>
#include <math.h>
#include <stdint.h>

// ---------------------------------------------------------------------------
// MultiHeadAttention B=2, S=1024, D=1024 (effective 64 heads x dim 16).
//  0) conv_kernel : X inputs and W -> single fp16 word-planes
//  1) qkv GEMMs   : fp16 m16n8k16, 3-stage cp.async pipeline, 2 CTAs/SM
//  2) attention   : fp16 flash kernel, 512 thr / 512 q-rows per CTA
//                   (halved K/V staging), double-buffered tiles w/ 1 sync,
//                   softmax via ex2.approx.f16x2, fp32 row sums
//  3) out GEMM    : ctx @ Wo fp16, 512 threads, 3-stage cp.async
// ---------------------------------------------------------------------------

#define BDIM   2
#define SEQ    1024
#define DMODEL 1024
#define MROWS  (BDIM * SEQ)
#define NHEADS 64
#define EDIM   16
#define XW     (MROWS * DMODEL / 2)
#define WW     (DMODEL * DMODEL / 2)

__device__ unsigned g_xw[3 * XW];
__device__ unsigned g_ww[4 * WW];
__device__ unsigned g_qw[XW], g_kw[XW], g_vw[XW];
__device__ unsigned g_cw[XW];

// ---------------------------------------------------------------------------
// helpers
// ---------------------------------------------------------------------------
__device__ __forceinline__ unsigned packh(float x, float y) {
    __half2 h = __float22half2_rn(make_float2(x, y));
    return *reinterpret_cast<unsigned*>(&h);
}
__device__ __forceinline__ float2 unpackh(unsigned u) {
    __half2 h = *reinterpret_cast<__half2*>(&u);
    return __half22float2(h);
}
__device__ __forceinline__ uint32_t smem_u32(const void* p) {
    uint32_t a;
    asm("{ .reg .u64 t; cvta.to.shared.u64 t, %1; cvt.u32.u64 %0, t; }"
        : "=r"(a) : "l"(p));
    return a;
}

#define LDSM4(d0, d1, d2, d3, a) \
    asm volatile("ldmatrix.sync.aligned.m8n8.x4.shared.b16 {%0,%1,%2,%3}, [%4];" \
                 : "=r"(d0), "=r"(d1), "=r"(d2), "=r"(d3) : "r"(a))

#define CP16(dst, src) \
    asm volatile("cp.async.cg.shared.global [%0], [%1], 16;" :: "r"(dst), "l"(src))
#define CP_COMMIT() asm volatile("cp.async.commit_group;" ::: "memory")
#define CP_WAIT1()  asm volatile("cp.async.wait_group 1;" ::: "memory")
#define CP_WAIT0()  asm volatile("cp.async.wait_group 0;" ::: "memory")

__device__ __forceinline__ void mma_f16(float c[4],
                                        const unsigned a[4],
                                        unsigned b0, unsigned b1) {
    asm volatile(
        "mma.sync.aligned.m16n8k16.row.col.f32.f16.f16.f32 "
        "{%0,%1,%2,%3}, {%4,%5,%6,%7}, {%8,%9}, {%0,%1,%2,%3};"
        : "+f"(c[0]), "+f"(c[1]), "+f"(c[2]), "+f"(c[3])
        : "r"(a[0]), "r"(a[1]), "r"(a[2]), "r"(a[3]), "r"(b0), "r"(b1));
}

#define EX2_H2(d, a) \
    asm volatile("ex2.approx.f16x2 %0, %1;" : "=r"(d) : "r"(a))
#define MUL_H2(d, a, b) \
    asm volatile("mul.rn.f16x2 %0, %1, %2;" : "=r"(d) : "r"(a), "r"(b))

// ---------------------------------------------------------------------------
// conv kernel (R15-proven)
// ---------------------------------------------------------------------------
__global__ __launch_bounds__(256)
void conv_kernel(const float* __restrict__ Q, const float* __restrict__ K,
                 const float* __restrict__ V,
                 const float* __restrict__ Wq, const float* __restrict__ Wk,
                 const float* __restrict__ Wv, const float* __restrict__ Wo)
{
    const int z = blockIdx.z;
    const float* src;
    unsigned* dst;
    int n;
    if (z < 3) {
        src = (z == 0) ? Q : (z == 1) ? K : V;
        dst = g_xw + (size_t)z * XW;
        n = MROWS * DMODEL;
    } else {
        src = (z == 3) ? Wq : (z == 4) ? Wk : (z == 5) ? Wv : Wo;
        dst = g_ww + (size_t)(z - 3) * WW;
        n = DMODEL * DMODEL;
    }
    const int i8 = (blockIdx.x * 256 + threadIdx.x) * 8;
    if (i8 >= n) return;
    float4 a = *(const float4*)(src + i8);
    float4 b = *(const float4*)(src + i8 + 4);
    *(uint4*)(dst + (i8 >> 1)) =
        make_uint4(packh(a.x, a.y), packh(a.z, a.w),
                   packh(b.x, b.y), packh(b.z, b.w));
}

// ---------------------------------------------------------------------------
// qkv GEMM (R15-proven): CTA 128x128, 256 thr, 3-stage cp.async.
// ---------------------------------------------------------------------------
#define GSTAGE 20480
#define GSMEM  (3 * GSTAGE)

__global__ __launch_bounds__(256, 2)
void qkv_gemm(const float* __restrict__ bq, const float* __restrict__ bk,
              const float* __restrict__ bv)
{
    const int z = blockIdx.z;
    const unsigned* Aw = g_xw + (size_t)z * XW;
    const unsigned* Ww = g_ww + (size_t)z * WW;
    const float* bias = (z == 0) ? bq : (z == 1) ? bk : bv;
    unsigned* Cw = (z == 0) ? g_qw : (z == 1) ? g_kw : g_vw;

    extern __shared__ __align__(16) unsigned char smem[];
    const uint32_t su = smem_u32(smem);

    const int tid  = threadIdx.x;
    const int warp = tid >> 5;
    const int lane = tid & 31;
    const int g    = lane >> 2;
    const int q    = lane & 3;
    const int wrow = (warp >> 2) * 64;
    const int wcol = (warp & 3) * 32;
    const int byBase = blockIdx.y * 128;
    const int bxBase = blockIdx.x * 128;

    const int r    = lane & 7;
    const int sel  = lane >> 3;
    const int aRow = r + ((sel & 1) ? 8 : 0);
    const int aK   = (sel >> 1) ? 16 : 0;
    const int bRow = r + ((sel >> 1) ? 8 : 0);
    const int bK   = (sel & 1) ? 16 : 0;

    const int ar = tid >> 1;
    const int as = tid & 1;
    const unsigned* Ap = Aw + (size_t)(byBase + ar) * 512 + as * 8;
    const unsigned* Wp = Ww + (size_t)(bxBase + ar) * 512 + as * 8;

    auto issue = [&](int c) {
        const uint32_t sb = su + (c % 3) * GSTAGE;
        const int kw = c * 16;
        CP16(sb + ar * 80 + as * 32,              Ap + kw);
        CP16(sb + ar * 80 + as * 32 + 16,         Ap + kw + 4);
        CP16(sb + 10240 + ar * 80 + as * 32,      Wp + kw);
        CP16(sb + 10240 + ar * 80 + as * 32 + 16, Wp + kw + 4);
        CP_COMMIT();
    };

    float acc[4][4][4];
#pragma unroll
    for (int mt = 0; mt < 4; mt++)
#pragma unroll
        for (int nt = 0; nt < 4; nt++)
#pragma unroll
            for (int e = 0; e < 4; e++) acc[mt][nt][e] = 0.f;

    issue(0);
    issue(1);

    for (int c = 0; c < 32; c++) {
        if (c < 31) { CP_WAIT1(); } else { CP_WAIT0(); }
        __syncthreads();
        const uint32_t sb = su + (c % 3) * GSTAGE;

#pragma unroll
        for (int ks = 0; ks < 2; ks++) {
            const int kB = ks * 32;
            unsigned fa[4][4];
#pragma unroll
            for (int mt = 0; mt < 4; mt++)
                LDSM4(fa[mt][0], fa[mt][1], fa[mt][2], fa[mt][3],
                      sb + (wrow + mt * 16 + aRow) * 80 + kB + aK);
            unsigned nb[4][2];
#pragma unroll
            for (int p = 0; p < 2; p++) {
                unsigned t0, t1, t2, t3;
                LDSM4(t0, t1, t2, t3,
                      sb + 10240 + (wcol + p * 16 + bRow) * 80 + kB + bK);
                nb[2 * p][0] = t0; nb[2 * p][1] = t1;
                nb[2 * p + 1][0] = t2; nb[2 * p + 1][1] = t3;
            }
#pragma unroll
            for (int nt = 0; nt < 4; nt++)
#pragma unroll
                for (int mt = 0; mt < 4; mt++)
                    mma_f16(acc[mt][nt], fa[mt], nb[nt][0], nb[nt][1]);
        }
        if (c + 2 < 32) issue(c + 2);
    }

#pragma unroll
    for (int nt = 0; nt < 4; nt++) {
        const int col = bxBase + wcol + nt * 8 + 2 * q;
        const float2 bb = *(const float2*)&bias[col];
#pragma unroll
        for (int mt = 0; mt < 4; mt++) {
            const int row = byBase + wrow + mt * 16 + g;
            Cw[(size_t)row * 512 + (col >> 1)] =
                packh(acc[mt][nt][0] + bb.x, acc[mt][nt][1] + bb.y);
            Cw[(size_t)(row + 8) * 512 + (col >> 1)] =
                packh(acc[mt][nt][2] + bb.x, acc[mt][nt][3] + bb.y);
        }
    }
}

// ---------------------------------------------------------------------------
// out GEMM (R15-proven): CTA 128x128, 512 threads, 3-stage cp.async.
// ---------------------------------------------------------------------------
__global__ __launch_bounds__(512, 1)
void out_gemm(const float* __restrict__ bo, float* __restrict__ out)
{
    const unsigned* Aw = g_cw;
    const unsigned* Ww = g_ww + (size_t)3 * WW;

    extern __shared__ __align__(16) unsigned char smem[];
    const uint32_t su = smem_u32(smem);

    const int tid  = threadIdx.x;
    const int warp = tid >> 5;
    const int lane = tid & 31;
    const int g    = lane >> 2;
    const int q    = lane & 3;
    const int wrow = (warp >> 2) * 32;
    const int wcol = (warp & 3) * 32;
    const int byBase = blockIdx.y * 128;
    const int bxBase = blockIdx.x * 128;

    const int r    = lane & 7;
    const int sel  = lane >> 3;
    const int aRow = r + ((sel & 1) ? 8 : 0);
    const int aK   = (sel >> 1) ? 16 : 0;
    const int bRow = r + ((sel >> 1) ? 8 : 0);
    const int bK   = (sel & 1) ? 16 : 0;

    const int ar = tid >> 2;
    const int as = tid & 3;
    const unsigned* Ap = Aw + (size_t)(byBase + ar) * 512 + as * 4;
    const unsigned* Wp = Ww + (size_t)(bxBase + ar) * 512 + as * 4;

    auto issue = [&](int c) {
        const uint32_t sb = su + (c % 3) * GSTAGE;
        const int kw = c * 16;
        CP16(sb + ar * 80 + as * 16,         Ap + kw);
        CP16(sb + 10240 + ar * 80 + as * 16, Wp + kw);
        CP_COMMIT();
    };

    float acc[2][4][4];
#pragma unroll
    for (int mt = 0; mt < 2; mt++)
#pragma unroll
        for (int nt = 0; nt < 4; nt++)
#pragma unroll
            for (int e = 0; e < 4; e++) acc[mt][nt][e] = 0.f;

    issue(0);
    issue(1);

    for (int c = 0; c < 32; c++) {
        if (c < 31) { CP_WAIT1(); } else { CP_WAIT0(); }
        __syncthreads();
        const uint32_t sb = su + (c % 3) * GSTAGE;

#pragma unroll
        for (int ks = 0; ks < 2; ks++) {
            const int kB = ks * 32;
            unsigned fa[2][4];
#pragma unroll
            for (int mt = 0; mt < 2; mt++)
                LDSM4(fa[mt][0], fa[mt][1], fa[mt][2], fa[mt][3],
                      sb + (wrow + mt * 16 + aRow) * 80 + kB + aK);
            unsigned nb[4][2];
#pragma unroll
            for (int p = 0; p < 2; p++) {
                unsigned t0, t1, t2, t3;
                LDSM4(t0, t1, t2, t3,
                      sb + 10240 + (wcol + p * 16 + bRow) * 80 + kB + bK);
                nb[2 * p][0] = t0; nb[2 * p][1] = t1;
                nb[2 * p + 1][0] = t2; nb[2 * p + 1][1] = t3;
            }
#pragma unroll
            for (int nt = 0; nt < 4; nt++)
#pragma unroll
                for (int mt = 0; mt < 2; mt++)
                    mma_f16(acc[mt][nt], fa[mt], nb[nt][0], nb[nt][1]);
        }
        if (c + 2 < 32) issue(c + 2);
    }

#pragma unroll
    for (int nt = 0; nt < 4; nt++) {
        const int col = bxBase + wcol + nt * 8 + 2 * q;
        const float2 bb = *(const float2*)&bo[col];
#pragma unroll
        for (int mt = 0; mt < 2; mt++) {
            const int row = byBase + wrow + mt * 16 + g;
            *(float2*)&out[(size_t)row * DMODEL + col] =
                make_float2(acc[mt][nt][0] + bb.x, acc[mt][nt][1] + bb.y);
            *(float2*)&out[(size_t)(row + 8) * DMODEL + col] =
                make_float2(acc[mt][nt][2] + bb.x, acc[mt][nt][3] + bb.y);
        }
    }
}

// ---------------------------------------------------------------------------
// Attention: grid (S/512, 64, 2) = (2, 64, 2), 512 threads (16 warps),
// warp = 32 q rows -> 512 rows per CTA (K/V staging traffic halved).
// Double-buffered K/V tiles, ONE sync per tile (plain STS).
// Softmax via ex2.approx.f16x2; fp32 row sums; ctx fp16 plane.
// ---------------------------------------------------------------------------
#define KT 64
#define NTILES (SEQ / KT)

__global__ __launch_bounds__(512, 1)
void attn_kernel()
{
    const int h    = blockIdx.y;
    const int b    = blockIdx.z;
    const int tid  = threadIdx.x;
    const int warp = tid >> 5;
    const int lane = tid & 31;
    const int g    = lane >> 2;
    const int q    = lane & 3;

    __shared__ unsigned Kh[2][KT][12];
    __shared__ unsigned Vth[2][EDIM][36];

    const int hw      = h * 8;
    const size_t bRow = (size_t)b * SEQ;

    const unsigned hs = packh(0.04508422f, 0.04508422f);  // log2e/32

    const int rowBase = blockIdx.x * 512 + warp * 32;
    unsigned qf[2][4];
#pragma unroll
    for (int mt = 0; mt < 2; mt++) {
        const size_t r0 = bRow + rowBase + mt * 16 + g;
        const size_t w0 = r0 * 512 + hw;
        const size_t w1 = (r0 + 8) * 512 + hw;
        qf[mt][0] = g_qw[w0 + q];
        qf[mt][1] = g_qw[w1 + q];
        qf[mt][2] = g_qw[w0 + 4 + q];
        qf[mt][3] = g_qw[w1 + 4 + q];
    }

    float oacc[2][2][4];
#pragma unroll
    for (int mt = 0; mt < 2; mt++)
#pragma unroll
        for (int ne = 0; ne < 2; ne++)
#pragma unroll
            for (int e = 0; e < 4; e++) oacc[mt][ne][e] = 0.f;
    float lsum[2][2] = {{0.f, 0.f}, {0.f, 0.f}};

    // staging split: threads 0..255 -> K tile, threads 256..511 -> V^T tile
    auto stage = [&](int kt, int buf) {
        if (tid < 256) {
            const int key  = tid >> 2;
            const int quad = tid & 3;
            *(uint2*)&Kh[buf][key][2 * quad] =
                *(const uint2*)&g_kw[(bRow + kt + key) * 512 + hw + 2 * quad];
        } else {
            const int t  = tid - 256;
            const int e  = t & 15;
            const int k0 = t >> 4;                 // 0..15
            const unsigned short* vh = (const unsigned short*)g_vw;
#pragma unroll
            for (int rep = 0; rep < 2; rep++) {
                const int kp = k0 + rep * 16;      // 0..31
                const size_t h0 = (bRow + kt + 2 * kp) * 1024 + (size_t)hw * 2 + e;
                Vth[buf][e][kp] = (unsigned)vh[h0] | ((unsigned)vh[h0 + 1024] << 16);
            }
        }
    };

    stage(0, 0);

    for (int t = 0; t < NTILES; t++) {
        __syncthreads();
        if (t + 1 < NTILES) stage((t + 1) * KT, (t + 1) & 1);
        const int buf = t & 1;

        float s[2][8][4];
#pragma unroll
        for (int mt = 0; mt < 2; mt++)
#pragma unroll
            for (int nt = 0; nt < 8; nt++)
#pragma unroll
                for (int e = 0; e < 4; e++) s[mt][nt][e] = 0.f;

#pragma unroll
        for (int nt = 0; nt < 8; nt++) {
            const int n = nt * 8 + g;
            unsigned kb0 = Kh[buf][n][q], kb1 = Kh[buf][n][4 + q];
#pragma unroll
            for (int mt = 0; mt < 2; mt++)
                mma_f16(s[mt][nt], qf[mt], kb0, kb1);
        }

        unsigned pw[2][8][2];
#pragma unroll
        for (int mt = 0; mt < 2; mt++)
#pragma unroll
            for (int nt = 0; nt < 8; nt++) {
                unsigned u0 = packh(s[mt][nt][0], s[mt][nt][1]);
                unsigned u1 = packh(s[mt][nt][2], s[mt][nt][3]);
                MUL_H2(u0, u0, hs);
                MUL_H2(u1, u1, hs);
                EX2_H2(pw[mt][nt][0], u0);
                EX2_H2(pw[mt][nt][1], u1);
                float2 f0 = unpackh(pw[mt][nt][0]);
                float2 f1 = unpackh(pw[mt][nt][1]);
                lsum[mt][0] += f0.x + f0.y;
                lsum[mt][1] += f1.x + f1.y;
            }

#pragma unroll
        for (int kt2 = 0; kt2 < 4; kt2++) {
            unsigned pa[2][4];
#pragma unroll
            for (int mt = 0; mt < 2; mt++) {
                pa[mt][0] = pw[mt][2 * kt2][0];
                pa[mt][1] = pw[mt][2 * kt2][1];
                pa[mt][2] = pw[mt][2 * kt2 + 1][0];
                pa[mt][3] = pw[mt][2 * kt2 + 1][1];
            }
#pragma unroll
            for (int ne = 0; ne < 2; ne++) {
                const int er = ne * 8 + g;
                unsigned vb0 = Vth[buf][er][kt2 * 8 + q];
                unsigned vb1 = Vth[buf][er][kt2 * 8 + 4 + q];
#pragma unroll
                for (int mt = 0; mt < 2; mt++)
                    mma_f16(oacc[mt][ne], pa[mt], vb0, vb1);
            }
        }
    }

#pragma unroll
    for (int mt = 0; mt < 2; mt++)
#pragma unroll
        for (int rr = 0; rr < 2; rr++) {
            float v = lsum[mt][rr];
            v += __shfl_xor_sync(0xFFFFFFFF, v, 1);
            v += __shfl_xor_sync(0xFFFFFFFF, v, 2);
            lsum[mt][rr] = 1.0f / v;
        }

#pragma unroll
    for (int mt = 0; mt < 2; mt++) {
        const size_t r0 = bRow + rowBase + mt * 16 + g;
#pragma unroll
        for (int ne = 0; ne < 2; ne++) {
            const int colw = ne * 4 + q;
            g_cw[r0 * 512 + hw + colw] =
                packh(oacc[mt][ne][0] * lsum[mt][0], oacc[mt][ne][1] * lsum[mt][0]);
            g_cw[(r0 + 8) * 512 + hw + colw] =
                packh(oacc[mt][ne][2] * lsum[mt][1], oacc[mt][ne][3] * lsum[mt][1]);
        }
    }
}

// ---------------------------------------------------------------------------
// kernel_launch: inputs 0:Q 1:K 2:V 3:Wq 4:bq 5:Wk 6:bk 7:Wv 8:bv 9:Wo 10:bo
// ---------------------------------------------------------------------------
extern "C" void kernel_launch(void* const* d_in, const int* in_sizes, int n_in,
                              void* d_out, int out_size)
{
    (void)in_sizes; (void)n_in; (void)out_size;
    const float* Q  = (const float*)d_in[0];
    const float* K  = (const float*)d_in[1];
    const float* V  = (const float*)d_in[2];
    const float* Wq = (const float*)d_in[3];
    const float* bq = (const float*)d_in[4];
    const float* Wk = (const float*)d_in[5];
    const float* bk = (const float*)d_in[6];
    const float* Wv = (const float*)d_in[7];
    const float* bv = (const float*)d_in[8];
    const float* Wo = (const float*)d_in[9];
    const float* bo = (const float*)d_in[10];
    float* out = (float*)d_out;

    cudaFuncSetAttribute(qkv_gemm, cudaFuncAttributeMaxDynamicSharedMemorySize, GSMEM);
    cudaFuncSetAttribute(out_gemm, cudaFuncAttributeMaxDynamicSharedMemorySize, GSMEM);

    dim3 gconv(1024, 1, 7);
    conv_kernel<<<gconv, 256>>>(Q, K, V, Wq, Wk, Wv, Wo);

    dim3 gqkv(DMODEL / 128, MROWS / 128, 3);   // (8, 16, 3)
    qkv_gemm<<<gqkv, 256, GSMEM>>>(bq, bk, bv);

    dim3 gattn(SEQ / 512, NHEADS, BDIM);       // (2, 64, 2)
    attn_kernel<<<gattn, 512>>>();

    dim3 gout(DMODEL / 128, MROWS / 128);      // (8, 16)
    out_gemm<<<gout, 512, GSMEM>>>(bo, out);
}

// round 17
// speedup vs baseline: 1.0806x; 1.0806x over previous
#include <cuda_runtime.h>
#include <cuda_fp16.h>
#include <math.h>
#include <stdint.h>

// ---------------------------------------------------------------------------
// MultiHeadAttention B=2, S=1024, D=1024 (effective 64 heads x dim 16).
//  0) conv_kernel : X inputs and W -> single fp16 word-planes
//  1) qkv GEMMs   : fp16 m16n8k16, 3-stage cp.async pipeline, 2 CTAs/SM
//  2) attention   : fp16 flash kernel (R15 shape: 256 thr, grid (4,64,2)),
//                   register-prefetch double-buffered staging (1 sync/tile),
//                   softmax via ex2.approx.f16x2, fp32 row sums
//  3) out GEMM    : ctx @ Wo fp16, 512 threads, 3-stage cp.async
// ---------------------------------------------------------------------------

#define BDIM   2
#define SEQ    1024
#define DMODEL 1024
#define MROWS  (BDIM * SEQ)
#define NHEADS 64
#define EDIM   16
#define XW     (MROWS * DMODEL / 2)
#define WW     (DMODEL * DMODEL / 2)

__device__ unsigned g_xw[3 * XW];
__device__ unsigned g_ww[4 * WW];
__device__ unsigned g_qw[XW], g_kw[XW], g_vw[XW];
__device__ unsigned g_cw[XW];

// ---------------------------------------------------------------------------
// helpers
// ---------------------------------------------------------------------------
__device__ __forceinline__ unsigned packh(float x, float y) {
    __half2 h = __float22half2_rn(make_float2(x, y));
    return *reinterpret_cast<unsigned*>(&h);
}
__device__ __forceinline__ float2 unpackh(unsigned u) {
    __half2 h = *reinterpret_cast<__half2*>(&u);
    return __half22float2(h);
}
__device__ __forceinline__ uint32_t smem_u32(const void* p) {
    uint32_t a;
    asm("{ .reg .u64 t; cvta.to.shared.u64 t, %1; cvt.u32.u64 %0, t; }"
        : "=r"(a) : "l"(p));
    return a;
}

#define LDSM4(d0, d1, d2, d3, a) \
    asm volatile("ldmatrix.sync.aligned.m8n8.x4.shared.b16 {%0,%1,%2,%3}, [%4];" \
                 : "=r"(d0), "=r"(d1), "=r"(d2), "=r"(d3) : "r"(a))

#define CP16(dst, src) \
    asm volatile("cp.async.cg.shared.global [%0], [%1], 16;" :: "r"(dst), "l"(src))
#define CP_COMMIT() asm volatile("cp.async.commit_group;" ::: "memory")
#define CP_WAIT1()  asm volatile("cp.async.wait_group 1;" ::: "memory")
#define CP_WAIT0()  asm volatile("cp.async.wait_group 0;" ::: "memory")

__device__ __forceinline__ void mma_f16(float c[4],
                                        const unsigned a[4],
                                        unsigned b0, unsigned b1) {
    asm volatile(
        "mma.sync.aligned.m16n8k16.row.col.f32.f16.f16.f32 "
        "{%0,%1,%2,%3}, {%4,%5,%6,%7}, {%8,%9}, {%0,%1,%2,%3};"
        : "+f"(c[0]), "+f"(c[1]), "+f"(c[2]), "+f"(c[3])
        : "r"(a[0]), "r"(a[1]), "r"(a[2]), "r"(a[3]), "r"(b0), "r"(b1));
}

#define EX2_H2(d, a) \
    asm volatile("ex2.approx.f16x2 %0, %1;" : "=r"(d) : "r"(a))
#define MUL_H2(d, a, b) \
    asm volatile("mul.rn.f16x2 %0, %1, %2;" : "=r"(d) : "r"(a), "r"(b))

// ---------------------------------------------------------------------------
// conv kernel (R15-proven)
// ---------------------------------------------------------------------------
__global__ __launch_bounds__(256)
void conv_kernel(const float* __restrict__ Q, const float* __restrict__ K,
                 const float* __restrict__ V,
                 const float* __restrict__ Wq, const float* __restrict__ Wk,
                 const float* __restrict__ Wv, const float* __restrict__ Wo)
{
    const int z = blockIdx.z;
    const float* src;
    unsigned* dst;
    int n;
    if (z < 3) {
        src = (z == 0) ? Q : (z == 1) ? K : V;
        dst = g_xw + (size_t)z * XW;
        n = MROWS * DMODEL;
    } else {
        src = (z == 3) ? Wq : (z == 4) ? Wk : (z == 5) ? Wv : Wo;
        dst = g_ww + (size_t)(z - 3) * WW;
        n = DMODEL * DMODEL;
    }
    const int i8 = (blockIdx.x * 256 + threadIdx.x) * 8;
    if (i8 >= n) return;
    float4 a = *(const float4*)(src + i8);
    float4 b = *(const float4*)(src + i8 + 4);
    *(uint4*)(dst + (i8 >> 1)) =
        make_uint4(packh(a.x, a.y), packh(a.z, a.w),
                   packh(b.x, b.y), packh(b.z, b.w));
}

// ---------------------------------------------------------------------------
// qkv GEMM (R15-proven): CTA 128x128, 256 thr, 3-stage cp.async.
// ---------------------------------------------------------------------------
#define GSTAGE 20480
#define GSMEM  (3 * GSTAGE)

__global__ __launch_bounds__(256, 2)
void qkv_gemm(const float* __restrict__ bq, const float* __restrict__ bk,
              const float* __restrict__ bv)
{
    const int z = blockIdx.z;
    const unsigned* Aw = g_xw + (size_t)z * XW;
    const unsigned* Ww = g_ww + (size_t)z * WW;
    const float* bias = (z == 0) ? bq : (z == 1) ? bk : bv;
    unsigned* Cw = (z == 0) ? g_qw : (z == 1) ? g_kw : g_vw;

    extern __shared__ __align__(16) unsigned char smem[];
    const uint32_t su = smem_u32(smem);

    const int tid  = threadIdx.x;
    const int warp = tid >> 5;
    const int lane = tid & 31;
    const int g    = lane >> 2;
    const int q    = lane & 3;
    const int wrow = (warp >> 2) * 64;
    const int wcol = (warp & 3) * 32;
    const int byBase = blockIdx.y * 128;
    const int bxBase = blockIdx.x * 128;

    const int r    = lane & 7;
    const int sel  = lane >> 3;
    const int aRow = r + ((sel & 1) ? 8 : 0);
    const int aK   = (sel >> 1) ? 16 : 0;
    const int bRow = r + ((sel >> 1) ? 8 : 0);
    const int bK   = (sel & 1) ? 16 : 0;

    const int ar = tid >> 1;
    const int as = tid & 1;
    const unsigned* Ap = Aw + (size_t)(byBase + ar) * 512 + as * 8;
    const unsigned* Wp = Ww + (size_t)(bxBase + ar) * 512 + as * 8;

    auto issue = [&](int c) {
        const uint32_t sb = su + (c % 3) * GSTAGE;
        const int kw = c * 16;
        CP16(sb + ar * 80 + as * 32,              Ap + kw);
        CP16(sb + ar * 80 + as * 32 + 16,         Ap + kw + 4);
        CP16(sb + 10240 + ar * 80 + as * 32,      Wp + kw);
        CP16(sb + 10240 + ar * 80 + as * 32 + 16, Wp + kw + 4);
        CP_COMMIT();
    };

    float acc[4][4][4];
#pragma unroll
    for (int mt = 0; mt < 4; mt++)
#pragma unroll
        for (int nt = 0; nt < 4; nt++)
#pragma unroll
            for (int e = 0; e < 4; e++) acc[mt][nt][e] = 0.f;

    issue(0);
    issue(1);

    for (int c = 0; c < 32; c++) {
        if (c < 31) { CP_WAIT1(); } else { CP_WAIT0(); }
        __syncthreads();
        const uint32_t sb = su + (c % 3) * GSTAGE;

#pragma unroll
        for (int ks = 0; ks < 2; ks++) {
            const int kB = ks * 32;
            unsigned fa[4][4];
#pragma unroll
            for (int mt = 0; mt < 4; mt++)
                LDSM4(fa[mt][0], fa[mt][1], fa[mt][2], fa[mt][3],
                      sb + (wrow + mt * 16 + aRow) * 80 + kB + aK);
            unsigned nb[4][2];
#pragma unroll
            for (int p = 0; p < 2; p++) {
                unsigned t0, t1, t2, t3;
                LDSM4(t0, t1, t2, t3,
                      sb + 10240 + (wcol + p * 16 + bRow) * 80 + kB + bK);
                nb[2 * p][0] = t0; nb[2 * p][1] = t1;
                nb[2 * p + 1][0] = t2; nb[2 * p + 1][1] = t3;
            }
#pragma unroll
            for (int nt = 0; nt < 4; nt++)
#pragma unroll
                for (int mt = 0; mt < 4; mt++)
                    mma_f16(acc[mt][nt], fa[mt], nb[nt][0], nb[nt][1]);
        }
        if (c + 2 < 32) issue(c + 2);
    }

#pragma unroll
    for (int nt = 0; nt < 4; nt++) {
        const int col = bxBase + wcol + nt * 8 + 2 * q;
        const float2 bb = *(const float2*)&bias[col];
#pragma unroll
        for (int mt = 0; mt < 4; mt++) {
            const int row = byBase + wrow + mt * 16 + g;
            Cw[(size_t)row * 512 + (col >> 1)] =
                packh(acc[mt][nt][0] + bb.x, acc[mt][nt][1] + bb.y);
            Cw[(size_t)(row + 8) * 512 + (col >> 1)] =
                packh(acc[mt][nt][2] + bb.x, acc[mt][nt][3] + bb.y);
        }
    }
}

// ---------------------------------------------------------------------------
// out GEMM (R15-proven): CTA 128x128, 512 threads, 3-stage cp.async.
// ---------------------------------------------------------------------------
__global__ __launch_bounds__(512, 1)
void out_gemm(const float* __restrict__ bo, float* __restrict__ out)
{
    const unsigned* Aw = g_cw;
    const unsigned* Ww = g_ww + (size_t)3 * WW;

    extern __shared__ __align__(16) unsigned char smem[];
    const uint32_t su = smem_u32(smem);

    const int tid  = threadIdx.x;
    const int warp = tid >> 5;
    const int lane = tid & 31;
    const int g    = lane >> 2;
    const int q    = lane & 3;
    const int wrow = (warp >> 2) * 32;
    const int wcol = (warp & 3) * 32;
    const int byBase = blockIdx.y * 128;
    const int bxBase = blockIdx.x * 128;

    const int r    = lane & 7;
    const int sel  = lane >> 3;
    const int aRow = r + ((sel & 1) ? 8 : 0);
    const int aK   = (sel >> 1) ? 16 : 0;
    const int bRow = r + ((sel >> 1) ? 8 : 0);
    const int bK   = (sel & 1) ? 16 : 0;

    const int ar = tid >> 2;
    const int as = tid & 3;
    const unsigned* Ap = Aw + (size_t)(byBase + ar) * 512 + as * 4;
    const unsigned* Wp = Ww + (size_t)(bxBase + ar) * 512 + as * 4;

    auto issue = [&](int c) {
        const uint32_t sb = su + (c % 3) * GSTAGE;
        const int kw = c * 16;
        CP16(sb + ar * 80 + as * 16,         Ap + kw);
        CP16(sb + 10240 + ar * 80 + as * 16, Wp + kw);
        CP_COMMIT();
    };

    float acc[2][4][4];
#pragma unroll
    for (int mt = 0; mt < 2; mt++)
#pragma unroll
        for (int nt = 0; nt < 4; nt++)
#pragma unroll
            for (int e = 0; e < 4; e++) acc[mt][nt][e] = 0.f;

    issue(0);
    issue(1);

    for (int c = 0; c < 32; c++) {
        if (c < 31) { CP_WAIT1(); } else { CP_WAIT0(); }
        __syncthreads();
        const uint32_t sb = su + (c % 3) * GSTAGE;

#pragma unroll
        for (int ks = 0; ks < 2; ks++) {
            const int kB = ks * 32;
            unsigned fa[2][4];
#pragma unroll
            for (int mt = 0; mt < 2; mt++)
                LDSM4(fa[mt][0], fa[mt][1], fa[mt][2], fa[mt][3],
                      sb + (wrow + mt * 16 + aRow) * 80 + kB + aK);
            unsigned nb[4][2];
#pragma unroll
            for (int p = 0; p < 2; p++) {
                unsigned t0, t1, t2, t3;
                LDSM4(t0, t1, t2, t3,
                      sb + 10240 + (wcol + p * 16 + bRow) * 80 + kB + bK);
                nb[2 * p][0] = t0; nb[2 * p][1] = t1;
                nb[2 * p + 1][0] = t2; nb[2 * p + 1][1] = t3;
            }
#pragma unroll
            for (int nt = 0; nt < 4; nt++)
#pragma unroll
                for (int mt = 0; mt < 2; mt++)
                    mma_f16(acc[mt][nt], fa[mt], nb[nt][0], nb[nt][1]);
        }
        if (c + 2 < 32) issue(c + 2);
    }

#pragma unroll
    for (int nt = 0; nt < 4; nt++) {
        const int col = bxBase + wcol + nt * 8 + 2 * q;
        const float2 bb = *(const float2*)&bo[col];
#pragma unroll
        for (int mt = 0; mt < 2; mt++) {
            const int row = byBase + wrow + mt * 16 + g;
            *(float2*)&out[(size_t)row * DMODEL + col] =
                make_float2(acc[mt][nt][0] + bb.x, acc[mt][nt][1] + bb.y);
            *(float2*)&out[(size_t)(row + 8) * DMODEL + col] =
                make_float2(acc[mt][nt][2] + bb.x, acc[mt][nt][3] + bb.y);
        }
    }
}

// ---------------------------------------------------------------------------
// Attention: grid (S/256, 64, 2) = (4, 64, 2), 256 threads, warp = 32 q rows,
// key tiles 64. Register-prefetch double-buffered staging, ONE sync per tile:
//   prefetch(0); loop{ STS(t); prefetch(t+1); sync; compute(t) }
// (STS(t) targets buf t&1 whose last readers, compute(t-2), finished before
//  iteration t-1's barrier -> race-free.)
// Softmax via ex2.approx.f16x2; fp32 row sums; ctx fp16 plane.
// ---------------------------------------------------------------------------
#define KT 64
#define NTILES (SEQ / KT)

__global__ __launch_bounds__(256)
void attn_kernel()
{
    const int h    = blockIdx.y;
    const int b    = blockIdx.z;
    const int tid  = threadIdx.x;
    const int warp = tid >> 5;
    const int lane = tid & 31;
    const int g    = lane >> 2;
    const int q    = lane & 3;

    __shared__ unsigned Kh[2][KT][12];
    __shared__ unsigned Vth[2][EDIM][36];

    const int hw      = h * 8;
    const size_t bRow = (size_t)b * SEQ;

    const unsigned hs = packh(0.04508422f, 0.04508422f);  // log2e/32

    const int rowBase = blockIdx.x * 256 + warp * 32;
    unsigned qf[2][4];
#pragma unroll
    for (int mt = 0; mt < 2; mt++) {
        const size_t r0 = bRow + rowBase + mt * 16 + g;
        const size_t w0 = r0 * 512 + hw;
        const size_t w1 = (r0 + 8) * 512 + hw;
        qf[mt][0] = g_qw[w0 + q];
        qf[mt][1] = g_qw[w1 + q];
        qf[mt][2] = g_qw[w0 + 4 + q];
        qf[mt][3] = g_qw[w1 + 4 + q];
    }

    float oacc[2][2][4];
#pragma unroll
    for (int mt = 0; mt < 2; mt++)
#pragma unroll
        for (int ne = 0; ne < 2; ne++)
#pragma unroll
            for (int e = 0; e < 4; e++) oacc[mt][ne][e] = 0.f;
    float lsum[2][2] = {{0.f, 0.f}, {0.f, 0.f}};

    // per-thread staging roles
    const int skey  = tid >> 2;            // K: key row 0..63
    const int squad = tid & 3;             // K: e-pair group
    const int se    = tid & 15;            // V: e index
    const int sk0   = tid >> 4;            // V: key-pair base 0..15

    const unsigned short* vhp = (const unsigned short*)g_vw;

    // prefetch registers
    uint2 pk;
    unsigned short pv0[2], pv1[2];

    auto prefetch = [&](int kt) {
        pk = *(const uint2*)&g_kw[(bRow + kt + skey) * 512 + hw + 2 * squad];
#pragma unroll
        for (int rep = 0; rep < 2; rep++) {
            const int kp = sk0 + rep * 16;
            const size_t h0 = (bRow + kt + 2 * kp) * 1024 + (size_t)hw * 2 + se;
            pv0[rep] = vhp[h0];
            pv1[rep] = vhp[h0 + 1024];
        }
    };
    auto store = [&](int buf) {
        *(uint2*)&Kh[buf][skey][2 * squad] = pk;
#pragma unroll
        for (int rep = 0; rep < 2; rep++)
            Vth[buf][se][sk0 + rep * 16] =
                (unsigned)pv0[rep] | ((unsigned)pv1[rep] << 16);
    };

    prefetch(0);

    for (int t = 0; t < NTILES; t++) {
        const int buf = t & 1;
        store(buf);
        if (t + 1 < NTILES) prefetch((t + 1) * KT);
        __syncthreads();

        float s[2][8][4];
#pragma unroll
        for (int mt = 0; mt < 2; mt++)
#pragma unroll
            for (int nt = 0; nt < 8; nt++)
#pragma unroll
                for (int e = 0; e < 4; e++) s[mt][nt][e] = 0.f;

#pragma unroll
        for (int nt = 0; nt < 8; nt++) {
            const int n = nt * 8 + g;
            unsigned kb0 = Kh[buf][n][q], kb1 = Kh[buf][n][4 + q];
#pragma unroll
            for (int mt = 0; mt < 2; mt++)
                mma_f16(s[mt][nt], qf[mt], kb0, kb1);
        }

        unsigned pw[2][8][2];
#pragma unroll
        for (int mt = 0; mt < 2; mt++)
#pragma unroll
            for (int nt = 0; nt < 8; nt++) {
                unsigned u0 = packh(s[mt][nt][0], s[mt][nt][1]);
                unsigned u1 = packh(s[mt][nt][2], s[mt][nt][3]);
                MUL_H2(u0, u0, hs);
                MUL_H2(u1, u1, hs);
                EX2_H2(pw[mt][nt][0], u0);
                EX2_H2(pw[mt][nt][1], u1);
                float2 f0 = unpackh(pw[mt][nt][0]);
                float2 f1 = unpackh(pw[mt][nt][1]);
                lsum[mt][0] += f0.x + f0.y;
                lsum[mt][1] += f1.x + f1.y;
            }

#pragma unroll
        for (int kt2 = 0; kt2 < 4; kt2++) {
            unsigned pa[2][4];
#pragma unroll
            for (int mt = 0; mt < 2; mt++) {
                pa[mt][0] = pw[mt][2 * kt2][0];
                pa[mt][1] = pw[mt][2 * kt2][1];
                pa[mt][2] = pw[mt][2 * kt2 + 1][0];
                pa[mt][3] = pw[mt][2 * kt2 + 1][1];
            }
#pragma unroll
            for (int ne = 0; ne < 2; ne++) {
                const int er = ne * 8 + g;
                unsigned vb0 = Vth[buf][er][kt2 * 8 + q];
                unsigned vb1 = Vth[buf][er][kt2 * 8 + 4 + q];
#pragma unroll
                for (int mt = 0; mt < 2; mt++)
                    mma_f16(oacc[mt][ne], pa[mt], vb0, vb1);
            }
        }
    }

#pragma unroll
    for (int mt = 0; mt < 2; mt++)
#pragma unroll
        for (int rr = 0; rr < 2; rr++) {
            float v = lsum[mt][rr];
            v += __shfl_xor_sync(0xFFFFFFFF, v, 1);
            v += __shfl_xor_sync(0xFFFFFFFF, v, 2);
            lsum[mt][rr] = 1.0f / v;
        }

#pragma unroll
    for (int mt = 0; mt < 2; mt++) {
        const size_t r0 = bRow + rowBase + mt * 16 + g;
#pragma unroll
        for (int ne = 0; ne < 2; ne++) {
            const int colw = ne * 4 + q;
            g_cw[r0 * 512 + hw + colw] =
                packh(oacc[mt][ne][0] * lsum[mt][0], oacc[mt][ne][1] * lsum[mt][0]);
            g_cw[(r0 + 8) * 512 + hw + colw] =
                packh(oacc[mt][ne][2] * lsum[mt][1], oacc[mt][ne][3] * lsum[mt][1]);
        }
    }
}

// ---------------------------------------------------------------------------
// kernel_launch: inputs 0:Q 1:K 2:V 3:Wq 4:bq 5:Wk 6:bk 7:Wv 8:bv 9:Wo 10:bo
// ---------------------------------------------------------------------------
extern "C" void kernel_launch(void* const* d_in, const int* in_sizes, int n_in,
                              void* d_out, int out_size)
{
    (void)in_sizes; (void)n_in; (void)out_size;
    const float* Q  = (const float*)d_in[0];
    const float* K  = (const float*)d_in[1];
    const float* V  = (const float*)d_in[2];
    const float* Wq = (const float*)d_in[3];
    const float* bq = (const float*)d_in[4];
    const float* Wk = (const float*)d_in[5];
    const float* bk = (const float*)d_in[6];
    const float* Wv = (const float*)d_in[7];
    const float* bv = (const float*)d_in[8];
    const float* Wo = (const float*)d_in[9];
    const float* bo = (const float*)d_in[10];
    float* out = (float*)d_out;

    cudaFuncSetAttribute(qkv_gemm, cudaFuncAttributeMaxDynamicSharedMemorySize, GSMEM);
    cudaFuncSetAttribute(out_gemm, cudaFuncAttributeMaxDynamicSharedMemorySize, GSMEM);

    dim3 gconv(1024, 1, 7);
    conv_kernel<<<gconv, 256>>>(Q, K, V, Wq, Wk, Wv, Wo);

    dim3 gqkv(DMODEL / 128, MROWS / 128, 3);   // (8, 16, 3)
    qkv_gemm<<<gqkv, 256, GSMEM>>>(bq, bk, bv);

    dim3 gattn(SEQ / 256, NHEADS, BDIM);       // (4, 64, 2)
    attn_kernel<<<gattn, 256>>>();

    dim3 gout(DMODEL / 128, MROWS / 128);      // (8, 16)
    out_gemm<<<gout, 512, GSMEM>>>(bo, out);
}